// round 8
// baseline (speedup 1.0000x reference)
#include <cuda_runtime.h>
#include <cuda_bf16.h>
#include <cstdint>

#define NB 32
#define E  512
#define IND 128
#define OUTD 64
#define NT 3
#define QD 128
#define CD 128   // 2*OUTD

// ---------------- scratch (__device__ globals: no allocs allowed) ----------
__device__ float g_wsrc[NT*NB*IND];
__device__ float g_wdst[NT*NB*IND];
__device__ float g_ssrc[NT*NB*E];
__device__ float g_sdst[NT*NB*E];
__device__ float g_rmax[NB*E];
__device__ float g_rinvZ[NB*E];
// H transposed, bf16 hi/lo split: [n][d][e]
__device__ __nv_bfloat16 g_hmT_hi[(size_t)NB*OUTD*E];
__device__ __nv_bfloat16 g_hmT_lo[(size_t)NB*OUTD*E];
__device__ float g_part[(size_t)3*NB*E*OUTD];       // split-K partials (kz=1..3)
__device__ unsigned char g_adj8[(size_t)NB*E*E];    // packed adj (values 0..3)

// ---------------- fast exp on FMA/ALU pipes (no MUFU) -----------------------
__device__ __forceinline__ float fexp(float s) {
    float x = fmaxf(s * 1.4426950408889634f, -127.f);
    float r  = __fadd_rn(x, 12582912.f);            // round-to-nearest int
    float nf = __fadd_rn(r, -12582912.f);
    float f  = x - nf;                              // f in [-0.5, 0.5]
    int   n  = __float_as_int(r);                   // 0x4B400000 + k
    float sc = __int_as_float((n + (127 - 0x4B400000)) << 23);  // 2^k
    float p = 1.3333558e-3f;
    p = fmaf(p, f, 9.6181291e-3f);
    p = fmaf(p, f, 5.5504109e-2f);
    p = fmaf(p, f, 2.4022651e-1f);
    p = fmaf(p, f, 6.9314718e-1f);
    p = fmaf(p, f, 1.0f);
    return p * sc;
}

__device__ __forceinline__ uint32_t smem_u32(const void* p) {
    uint32_t a;
    asm("{ .reg .u64 t; cvta.to.shared.u64 t, %1; cvt.u32.u64 %0, t; }"
        : "=r"(a) : "l"(p));
    return a;
}

#define LDSM4_T(R, addr) \
    asm volatile("ldmatrix.sync.aligned.m8n8.x4.trans.shared.b16 {%0,%1,%2,%3}, [%4];" \
        : "=r"((R)[0]), "=r"((R)[1]), "=r"((R)[2]), "=r"((R)[3]) : "r"(addr))
#define LDSM4(R, addr) \
    asm volatile("ldmatrix.sync.aligned.m8n8.x4.shared.b16 {%0,%1,%2,%3}, [%4];" \
        : "=r"((R)[0]), "=r"((R)[1]), "=r"((R)[2]), "=r"((R)[3]) : "r"(addr))
#define MMA16816(d, a, b0v, b1v) \
    asm volatile("mma.sync.aligned.m16n8k16.row.col.f32.bf16.bf16.f32 " \
        "{%0,%1,%2,%3}, {%4,%5,%6,%7}, {%8,%9}, {%0,%1,%2,%3};" \
        : "+f"((d)[0]), "+f"((d)[1]), "+f"((d)[2]), "+f"((d)[3]) \
        : "r"((a)[0]), "r"((a)[1]), "r"((a)[2]), "r"((a)[3]), "r"(b0v), "r"(b1v))

// ---------------------------------------------------------------------------
// Kernel 1: per (t,n) fold qg*a into 128-vectors w_src/w_dst
// ---------------------------------------------------------------------------
__global__ void prep_kernel(const float* __restrict__ qv,
                            const float* __restrict__ Wt,
                            const float* __restrict__ at,
                            const float* __restrict__ W1,
                            const float* __restrict__ W2) {
    int t = blockIdx.x / NB, n = blockIdx.x % NB;
    int c = threadIdx.x;                       // 0..127
    __shared__ float sq[QD], sg1[CD], su[CD];

    sq[c] = qv[n*QD + c];
    __syncthreads();

    const float* w1 = W1 + t*QD*CD;
    float acc = 0.f;
    #pragma unroll 8
    for (int q = 0; q < QD; q++) acc += sq[q] * w1[q*CD + c];
    sg1[c] = fmaxf(acc, 0.f);
    __syncthreads();

    const float* w2 = W2 + t*CD*CD;
    acc = 0.f;
    #pragma unroll 8
    for (int q = 0; q < CD; q++) acc += sg1[q] * w2[q*CD + c];
    float qg = 1.f / (1.f + expf(-acc));
    su[c] = qg * at[t*CD + c];
    __syncthreads();

    const float* W = Wt + (t*IND + c)*OUTD;
    float ws = 0.f, wd = 0.f;
    #pragma unroll 8
    for (int o = 0; o < OUTD; o++) {
        float w = W[o];
        ws += w * su[o];
        wd += w * su[OUTD + o];
    }
    g_wsrc[(t*NB + n)*IND + c] = ws;
    g_wdst[(t*NB + n)*IND + c] = wd;
}

// ---------------------------------------------------------------------------
// Kernel 2 (fused): h = (x @ W_type[2]) * mask -> transposed bf16 hi/lo
// (coalesced 16B writes via smem transpose), and s_src/s_dst dots.
// ---------------------------------------------------------------------------
__global__ void hm_ssd_kernel(const float* __restrict__ x,
                              const float* __restrict__ Wt,
                              const float* __restrict__ mask) {
    __shared__ float Ws[IND][OUTD + 4];
    __shared__ float Xs[64][IND + 4];          // reused as Hs[64][65] in epilogue
    __shared__ float sw[6][IND];
    int n = blockIdx.x, e0 = blockIdx.y * 64;
    int tid = threadIdx.x;                     // 256

    const float4* Wg = (const float4*)(Wt + 2*IND*OUTD);
    for (int k = tid; k < IND*OUTD/4; k += 256) {
        float4 v = Wg[k];
        int row = (k*4) / OUTD, col = (k*4) % OUTD;
        *(float4*)&Ws[row][col] = v;
    }
    const float4* Xg = (const float4*)(x + ((size_t)n*E + e0)*IND);
    for (int k = tid; k < 64*IND/4; k += 256) {
        float4 v = Xg[k];
        int row = (k*4) / IND, col = (k*4) % IND;
        *(float4*)&Xs[row][col] = v;
    }
    for (int k = tid; k < 6*IND; k += 256) {
        int v = k / IND, i = k % IND;
        int t = v % 3;
        sw[v][i] = (v < 3) ? g_wsrc[(t*NB+n)*IND + i] : g_wdst[(t*NB+n)*IND + i];
    }
    __syncthreads();

    // ---- ssd part ----
    {
        int r = tid >> 2, q = tid & 3;
        float a[6] = {0.f,0.f,0.f,0.f,0.f,0.f};
        #pragma unroll 8
        for (int kk = 0; kk < 32; kk++) {
            int k = q + 4*kk;
            float xv = Xs[r][k];
            a[0] += xv * sw[0][k]; a[1] += xv * sw[1][k]; a[2] += xv * sw[2][k];
            a[3] += xv * sw[3][k]; a[4] += xv * sw[4][k]; a[5] += xv * sw[5][k];
        }
        #pragma unroll
        for (int off = 1; off <= 2; off <<= 1)
            #pragma unroll
            for (int u = 0; u < 6; u++)
                a[u] += __shfl_xor_sync(0xffffffffu, a[u], off);
        if (q == 0) {
            int e = e0 + r;
            #pragma unroll
            for (int t = 0; t < 3; t++) {
                g_ssrc[(t*NB+n)*E + e] = a[t];
                g_sdst[(t*NB+n)*E + e] = a[t+3];
            }
        }
    }

    // ---- GEMM 4x4 ----
    int dq = tid & 15, eq = tid >> 4;
    int d0 = dq*4, el = eq*4;
    float acc[4][4] = {};
    #pragma unroll 8
    for (int k = 0; k < IND; k++) {
        float4 b = *(const float4*)&Ws[k][d0];
        float a0 = Xs[el+0][k], a1 = Xs[el+1][k], a2 = Xs[el+2][k], a3 = Xs[el+3][k];
        acc[0][0]+=a0*b.x; acc[0][1]+=a0*b.y; acc[0][2]+=a0*b.z; acc[0][3]+=a0*b.w;
        acc[1][0]+=a1*b.x; acc[1][1]+=a1*b.y; acc[1][2]+=a1*b.z; acc[1][3]+=a1*b.w;
        acc[2][0]+=a2*b.x; acc[2][1]+=a2*b.y; acc[2][2]+=a2*b.z; acc[2][3]+=a2*b.w;
        acc[3][0]+=a3*b.x; acc[3][1]+=a3*b.y; acc[3][2]+=a3*b.z; acc[3][3]+=a3*b.w;
    }
    float mk0 = mask[n*E + e0 + el + 0];
    float mk1 = mask[n*E + e0 + el + 1];
    float mk2 = mask[n*E + e0 + el + 2];
    float mk3 = mask[n*E + e0 + el + 3];

    __syncthreads();                           // all Xs reads done; reuse as Hs
    float* HsB = &Xs[0][0];                    // Hs[e][d], row pitch 65
    #pragma unroll
    for (int dd = 0; dd < 4; dd++) {
        HsB[(el+0)*65 + d0+dd] = acc[0][dd]*mk0;
        HsB[(el+1)*65 + d0+dd] = acc[1][dd]*mk1;
        HsB[(el+2)*65 + d0+dd] = acc[2][dd]*mk2;
        HsB[(el+3)*65 + d0+dd] = acc[3][dd]*mk3;
    }
    __syncthreads();

    // coalesced 16B writes of both planes: task = (d, e-group of 8)
    #pragma unroll
    for (int u = 0; u < 2; u++) {
        int task = tid + u*256;                // 0..511
        int d = task >> 3, g = task & 7;
        uint32_t hv[4], lv[4];
        #pragma unroll
        for (int p = 0; p < 4; p++) {
            float v0 = HsB[(g*8 + 2*p + 0)*65 + d];
            float v1 = HsB[(g*8 + 2*p + 1)*65 + d];
            __nv_bfloat16 h0 = __float2bfloat16(v0);
            __nv_bfloat16 h1 = __float2bfloat16(v1);
            __nv_bfloat162 hp = __halves2bfloat162(h0, h1);
            hv[p] = *(uint32_t*)&hp;
            __nv_bfloat162 lp = __halves2bfloat162(
                __float2bfloat16(v0 - __bfloat162float(h0)),
                __float2bfloat16(v1 - __bfloat162float(h1)));
            lv[p] = *(uint32_t*)&lp;
        }
        size_t base = ((size_t)(n*OUTD + d))*E + e0 + g*8;
        *(uint4*)(g_hmT_hi + base) = make_uint4(hv[0], hv[1], hv[2], hv[3]);
        *(uint4*)(g_hmT_lo + base) = make_uint4(lv[0], lv[1], lv[2], lv[3]);
    }
}

// ---------------------------------------------------------------------------
// Kernel 3: row softmax stats, one warp per row, fexp; also packs adj->uint8
// ---------------------------------------------------------------------------
__global__ void rowstats_kernel(const int* __restrict__ adj) {
    int base = blockIdx.x * 16;
    int n = base / E;
    __shared__ float sds[3][E];
    int tid = threadIdx.x;
    #pragma unroll
    for (int k = tid; k < 3*E; k += 512)
        sds[k >> 9][k & 511] = g_sdst[((k >> 9)*NB + n)*E + (k & 511)];
    __syncthreads();

    int warp = tid >> 5, lane = tid & 31;
    int row = base + warp;
    int i = row & (E-1);
    float sr0 = g_ssrc[(0*NB+n)*E + i];
    float sr1 = g_ssrc[(1*NB+n)*E + i];
    float sr2 = g_ssrc[(2*NB+n)*E + i];
    const int* arow = adj + (size_t)row * E;
    unsigned char* a8 = g_adj8 + (size_t)row * E;

    float sc[16];
    #pragma unroll
    for (int k = 0; k < 16; k++) {
        int j = lane + 32*k;
        int v = arow[j];
        a8[j] = (unsigned char)v;              // pack for out_kernel
        float s = -1e30f;
        if (v > 0) {
            float srr = (v == 1) ? sr0 : ((v == 2) ? sr1 : sr2);
            float t2 = srr + sds[v-1][j];
            s = (t2 >= 0.f) ? t2 : 0.2f*t2;
        }
        sc[k] = s;
    }
    float m = sc[0];
    #pragma unroll
    for (int k = 1; k < 16; k++) m = fmaxf(m, sc[k]);
    #pragma unroll
    for (int off = 16; off > 0; off >>= 1) m = fmaxf(m, __shfl_xor_sync(~0u, m, off));
    float sum = 0.f;
    #pragma unroll
    for (int k = 0; k < 16; k++) sum += fexp(sc[k] - m);
    #pragma unroll
    for (int off = 16; off > 0; off >>= 1) sum += __shfl_xor_sync(~0u, sum, off);
    if (lane == 0) { g_rmax[row] = m; g_rinvZ[row] = 1.f / sum; }
}

// ---------------------------------------------------------------------------
// Kernel 4: output GEMM on tensor cores (mma.sync bf16, hi/lo 3-product),
// SPLIT-K by 4, adj read as packed uint8 (L2-hot, 1 reg per 8 rows).
// grid (NB, E/128, 4) = 512 blocks, 256 threads, 3 blocks/SM.
// ---------------------------------------------------------------------------
__global__ void __launch_bounds__(256, 3)
out_kernel(float* __restrict__ out) {
    extern __shared__ char sm[];
    const int CPL = 64*272;        // C plane bytes: 64 i-rows x (128+8) bf16
    const int HPL = 64*144;        // H plane bytes: 64 d-rows x (64+8) bf16
    char* Chi = sm;
    char* Hhi = sm + 2*CPL;
    char* Hlo = sm + 2*CPL + HPL;
    float* sds = (float*)(sm + 2*CPL + 2*HPL);  // [3][128]
    float* ssr = sds + 384;                      // [3][64]
    float* smx = ssr + 192;                      // [64]
    float* siz = smx + 64;                       // [64]

    const int n = blockIdx.x, j0t = blockIdx.y * 128, kz = blockIdx.z;
    const int tid = threadIdx.x;
    const int w = tid >> 5, lane = tid & 31;
    const int wm = w & 3, wn = w >> 2;           // warp tile: j=wm*32, d=wn*32

    const uint32_t sbase = smem_u32(sm);

    for (int k = tid; k < 384; k += 256)
        sds[k] = g_sdst[((k>>7)*NB + n)*E + j0t + (k & 127)];

    float acc[2][4][4] = {};                     // [m16 r][n8 ct][frag]

    const uint32_t lr = lane & 7;
    const uint32_t aA0 = sbase
        + (((lane>>4)&1)*8 + lr)*272
        + (wm*32 + ((lane>>3)&1)*8)*2;
    const uint32_t aB0 = sbase + 2*CPL
        + ((uint32_t)wn*32 + ((lane>>4)&1)*8 + lr)*144
        + ((lane>>3)&1)*16;

    for (int ch = 0; ch < 2; ch++) {
        const int ic = kz*128 + ch*64;
        __syncthreads();                         // prev chunk's mma reads done

        // batch this warp's packed-adj loads (1 uint per 8-row slot)
        const unsigned char* abase = g_adj8 + ((size_t)(n*E + ic))*E + j0t;
        uint32_t av[8];
        #pragma unroll
        for (int s = 0; s < 8; s++)
            av[s] = *(const uint32_t*)(abase + (size_t)(s*8 + w)*E + lane*4);

        // stage per-chunk stats
        for (int k = tid; k < 320; k += 256) {
            if (k < 192)      ssr[k]       = g_ssrc[((k>>6)*NB + n)*E + ic + (k & 63)];
            else if (k < 256) smx[k - 192] = g_rmax[n*E + ic + (k - 192)];
            else              siz[k - 256] = g_rinvZ[n*E + ic + (k - 256)];
        }
        // stage H^T hi/lo tiles
        #pragma unroll
        for (int u = 0; u < 2; u++) {
            int k = tid + u*256;
            int d = k >> 3, i16 = k & 7;
            size_t src = ((size_t)(n*OUTD + d))*E + ic + i16*8;
            *(uint4*)(Hhi + d*144 + i16*16) = *(const uint4*)(g_hmT_hi + src);
            *(uint4*)(Hlo + d*144 + i16*16) = *(const uint4*)(g_hmT_lo + src);
        }
        __syncthreads();

        // generate coef tile: warp w handles i rows {8s + w}
        #pragma unroll
        for (int s = 0; s < 8; s++) {
            int i = s*8 + w;
            uint32_t a4 = av[s];
            float m = smx[i], z = siz[i];
            float s0 = ssr[i], s1 = ssr[64 + i], s2 = ssr[128 + i];
            float cf[4];
            #pragma unroll
            for (int q = 0; q < 4; q++) {
                int v = (int)((a4 >> (8*q)) & 0xFFu);
                float score = -1e30f;
                if (v > 0) {
                    float srr = (v == 1) ? s0 : ((v == 2) ? s1 : s2);
                    float t2 = srr + sds[(v-1)*128 + lane*4 + q];
                    score = (t2 >= 0.f) ? t2 : 0.2f*t2;
                }
                cf[q] = fexp(score - m) * z;
            }
            __nv_bfloat16 h0 = __float2bfloat16(cf[0]), h1 = __float2bfloat16(cf[1]);
            __nv_bfloat16 h2 = __float2bfloat16(cf[2]), h3 = __float2bfloat16(cf[3]);
            uint2 hv;
            ((__nv_bfloat162*)&hv)[0] = __halves2bfloat162(h0, h1);
            ((__nv_bfloat162*)&hv)[1] = __halves2bfloat162(h2, h3);
            uint2 lv;
            ((__nv_bfloat162*)&lv)[0] = __halves2bfloat162(
                __float2bfloat16(cf[0] - __bfloat162float(h0)),
                __float2bfloat16(cf[1] - __bfloat162float(h1)));
            ((__nv_bfloat162*)&lv)[1] = __halves2bfloat162(
                __float2bfloat16(cf[2] - __bfloat162float(h2)),
                __float2bfloat16(cf[3] - __bfloat162float(h3)));
            *(uint2*)(Chi + i*272 + lane*8)       = hv;
            *(uint2*)(Chi + CPL + i*272 + lane*8) = lv;
        }
        __syncthreads();

        // mma phase: K-chunk = 4 k16 steps
        #pragma unroll
        for (int kk = 0; kk < 4; kk++) {
            uint32_t a_h[2][4], a_l[2][4];
            #pragma unroll
            for (int r = 0; r < 2; r++) {
                uint32_t ad = aA0 + kk*16*272 + r*32;
                LDSM4_T(a_h[r], ad);
                LDSM4_T(a_l[r], ad + CPL);
            }
            #pragma unroll
            for (int cp = 0; cp < 2; cp++) {
                uint32_t b_h[4], b_l[4];
                uint32_t bd = aB0 + cp*16*144 + kk*32;
                LDSM4(b_h, bd);
                LDSM4(b_l, bd + HPL);
                #pragma unroll
                for (int r = 0; r < 2; r++) {
                    float* d0 = acc[r][cp*2 + 0];
                    float* d1 = acc[r][cp*2 + 1];
                    MMA16816(d0, a_h[r], b_h[0], b_h[1]);
                    MMA16816(d0, a_h[r], b_l[0], b_l[1]);
                    MMA16816(d0, a_l[r], b_h[0], b_h[1]);
                    MMA16816(d1, a_h[r], b_h[2], b_h[3]);
                    MMA16816(d1, a_h[r], b_l[2], b_l[3]);
                    MMA16816(d1, a_l[r], b_h[2], b_h[3]);
                }
            }
        }
    }

    // epilogue
    float* dst = (kz == 0) ? out : (g_part + (size_t)(kz-1)*NB*E*OUTD);
    const int g = lane >> 2, t2 = (lane & 3)*2;
    #pragma unroll
    for (int r = 0; r < 2; r++) {
        #pragma unroll
        for (int ct = 0; ct < 4; ct++) {
            int j = j0t + wm*32 + r*16 + g;
            int d = wn*32 + ct*8 + t2;
            float* p = dst + ((size_t)(n*E + j))*OUTD + d;
            *(float2*)p = make_float2(acc[r][ct][0], acc[r][ct][1]);
            *(float2*)(p + 8*OUTD) = make_float2(acc[r][ct][2], acc[r][ct][3]);
        }
    }
}

// ---------------------------------------------------------------------------
// Kernel 5: out += sum of 3 partial slices
// ---------------------------------------------------------------------------
__global__ void combine_kernel(float* __restrict__ out) {
    const size_t S4 = (size_t)NB*E*OUTD/4;     // float4 stride
    size_t idx = (size_t)blockIdx.x*256 + threadIdx.x;
    float4 a  = ((const float4*)out)[idx];
    float4 p0 = ((const float4*)g_part)[idx];
    float4 p1 = ((const float4*)g_part)[idx + S4];
    float4 p2 = ((const float4*)g_part)[idx + 2*S4];
    a.x += p0.x + p1.x + p2.x;
    a.y += p0.y + p1.y + p2.y;
    a.z += p0.z + p1.z + p2.z;
    a.w += p0.w + p1.w + p2.w;
    ((float4*)out)[idx] = a;
}

// ---------------------------------------------------------------------------
extern "C" void kernel_launch(void* const* d_in, const int* in_sizes, int n_in,
                              void* d_out, int out_size) {
    const float* x    = (const float*)d_in[0];   // input_state (32,512,128)
    const int*   adj  = (const int*)  d_in[1];   // adj (32,512,512)
    const float* qv   = (const float*)d_in[2];   // query_vec (32,128)
    const float* mask = (const float*)d_in[3];   // node_mask (32,512,1)
    const float* Wt   = (const float*)d_in[4];   // W_type (3,128,64)
    const float* at   = (const float*)d_in[5];   // a_type (3,128,1)
    const float* W1   = (const float*)d_in[6];   // qattn_W1 (3,128,128)
    const float* W2   = (const float*)d_in[7];   // qattn_W2 (3,128,128)
    float* out = (float*)d_out;                  // (32,512,64)

    const int OUT_SMEM = 2*(64*272) + 2*(64*144) + (384 + 192 + 64 + 64)*4; // 56064
    cudaFuncSetAttribute(out_kernel, cudaFuncAttributeMaxDynamicSharedMemorySize,
                         OUT_SMEM);

    prep_kernel<<<NT*NB, 128>>>(qv, Wt, at, W1, W2);
    hm_ssd_kernel<<<dim3(NB, E/64), 256>>>(x, Wt, mask);
    rowstats_kernel<<<NB*E/16, 512>>>(adj);
    out_kernel<<<dim3(NB, E/128, 4), 256, OUT_SMEM>>>(out);
    combine_kernel<<<NB*E*OUTD/4/256, 256>>>(out);
}

// round 9
// speedup vs baseline: 1.2013x; 1.2013x over previous
#include <cuda_runtime.h>
#include <cuda_bf16.h>
#include <cstdint>

#define NB 32
#define E  512
#define IND 128
#define OUTD 64
#define NT 3
#define QD 128
#define CD 128   // 2*OUTD

// ---------------- scratch (__device__ globals: no allocs allowed) ----------
__device__ float g_wsrc[NT*NB*IND];
__device__ float g_wdst[NT*NB*IND];
__device__ float g_ssrc[NT*NB*E];
__device__ float g_sdst[NT*NB*E];
__device__ float g_rmax[NB*E];
__device__ float g_rinvZ[NB*E];
// H transposed, bf16 hi/lo split: [n][d][e]
__device__ __nv_bfloat16 g_hmT_hi[(size_t)NB*OUTD*E];
__device__ __nv_bfloat16 g_hmT_lo[(size_t)NB*OUTD*E];
__device__ unsigned char g_adj8[(size_t)NB*E*E];    // packed adj (values 0..3)

__device__ __forceinline__ uint32_t smem_u32(const void* p) {
    uint32_t a;
    asm("{ .reg .u64 t; cvta.to.shared.u64 t, %1; cvt.u32.u64 %0, t; }"
        : "=r"(a) : "l"(p));
    return a;
}

#define LDSM4_T(R, addr) \
    asm volatile("ldmatrix.sync.aligned.m8n8.x4.trans.shared.b16 {%0,%1,%2,%3}, [%4];" \
        : "=r"((R)[0]), "=r"((R)[1]), "=r"((R)[2]), "=r"((R)[3]) : "r"(addr))
#define LDSM4(R, addr) \
    asm volatile("ldmatrix.sync.aligned.m8n8.x4.shared.b16 {%0,%1,%2,%3}, [%4];" \
        : "=r"((R)[0]), "=r"((R)[1]), "=r"((R)[2]), "=r"((R)[3]) : "r"(addr))
#define MMA16816(d, a, b0v, b1v) \
    asm volatile("mma.sync.aligned.m16n8k16.row.col.f32.bf16.bf16.f32 " \
        "{%0,%1,%2,%3}, {%4,%5,%6,%7}, {%8,%9}, {%0,%1,%2,%3};" \
        : "+f"((d)[0]), "+f"((d)[1]), "+f"((d)[2]), "+f"((d)[3]) \
        : "r"((a)[0]), "r"((a)[1]), "r"((a)[2]), "r"((a)[3]), "r"(b0v), "r"(b1v))

// ---------------------------------------------------------------------------
// Kernel 1: per (t,n) fold qg*a into 128-vectors w_src/w_dst
// ---------------------------------------------------------------------------
__global__ void prep_kernel(const float* __restrict__ qv,
                            const float* __restrict__ Wt,
                            const float* __restrict__ at,
                            const float* __restrict__ W1,
                            const float* __restrict__ W2) {
    int t = blockIdx.x / NB, n = blockIdx.x % NB;
    int c = threadIdx.x;                       // 0..127
    __shared__ float sq[QD], sg1[CD], su[CD];

    sq[c] = qv[n*QD + c];
    __syncthreads();

    const float* w1 = W1 + t*QD*CD;
    float acc = 0.f;
    #pragma unroll 8
    for (int q = 0; q < QD; q++) acc += sq[q] * w1[q*CD + c];
    sg1[c] = fmaxf(acc, 0.f);
    __syncthreads();

    const float* w2 = W2 + t*CD*CD;
    acc = 0.f;
    #pragma unroll 8
    for (int q = 0; q < CD; q++) acc += sg1[q] * w2[q*CD + c];
    float qg = 1.f / (1.f + expf(-acc));
    su[c] = qg * at[t*CD + c];
    __syncthreads();

    const float* W = Wt + (t*IND + c)*OUTD;
    float ws = 0.f, wd = 0.f;
    #pragma unroll 8
    for (int o = 0; o < OUTD; o++) {
        float w = W[o];
        ws += w * su[o];
        wd += w * su[OUTD + o];
    }
    g_wsrc[(t*NB + n)*IND + c] = ws;
    g_wdst[(t*NB + n)*IND + c] = wd;
}

// ---------------------------------------------------------------------------
// Kernel 2 (fused): h = (x @ W_type[2]) * mask -> transposed bf16 hi/lo
// (coalesced 16B writes via smem transpose), and s_src/s_dst dots.
// ---------------------------------------------------------------------------
__global__ void hm_ssd_kernel(const float* __restrict__ x,
                              const float* __restrict__ Wt,
                              const float* __restrict__ mask) {
    __shared__ float Ws[IND][OUTD + 4];
    __shared__ float Xs[64][IND + 4];          // reused as Hs[64][65] in epilogue
    __shared__ float sw[6][IND];
    int n = blockIdx.x, e0 = blockIdx.y * 64;
    int tid = threadIdx.x;                     // 256

    const float4* Wg = (const float4*)(Wt + 2*IND*OUTD);
    for (int k = tid; k < IND*OUTD/4; k += 256) {
        float4 v = Wg[k];
        int row = (k*4) / OUTD, col = (k*4) % OUTD;
        *(float4*)&Ws[row][col] = v;
    }
    const float4* Xg = (const float4*)(x + ((size_t)n*E + e0)*IND);
    for (int k = tid; k < 64*IND/4; k += 256) {
        float4 v = Xg[k];
        int row = (k*4) / IND, col = (k*4) % IND;
        *(float4*)&Xs[row][col] = v;
    }
    for (int k = tid; k < 6*IND; k += 256) {
        int v = k / IND, i = k % IND;
        int t = v % 3;
        sw[v][i] = (v < 3) ? g_wsrc[(t*NB+n)*IND + i] : g_wdst[(t*NB+n)*IND + i];
    }
    __syncthreads();

    // ---- ssd part ----
    {
        int r = tid >> 2, q = tid & 3;
        float a[6] = {0.f,0.f,0.f,0.f,0.f,0.f};
        #pragma unroll 8
        for (int kk = 0; kk < 32; kk++) {
            int k = q + 4*kk;
            float xv = Xs[r][k];
            a[0] += xv * sw[0][k]; a[1] += xv * sw[1][k]; a[2] += xv * sw[2][k];
            a[3] += xv * sw[3][k]; a[4] += xv * sw[4][k]; a[5] += xv * sw[5][k];
        }
        #pragma unroll
        for (int off = 1; off <= 2; off <<= 1)
            #pragma unroll
            for (int u = 0; u < 6; u++)
                a[u] += __shfl_xor_sync(0xffffffffu, a[u], off);
        if (q == 0) {
            int e = e0 + r;
            #pragma unroll
            for (int t = 0; t < 3; t++) {
                g_ssrc[(t*NB+n)*E + e] = a[t];
                g_sdst[(t*NB+n)*E + e] = a[t+3];
            }
        }
    }

    // ---- GEMM 4x4 ----
    int dq = tid & 15, eq = tid >> 4;
    int d0 = dq*4, el = eq*4;
    float acc[4][4] = {};
    #pragma unroll 8
    for (int k = 0; k < IND; k++) {
        float4 b = *(const float4*)&Ws[k][d0];
        float a0 = Xs[el+0][k], a1 = Xs[el+1][k], a2 = Xs[el+2][k], a3 = Xs[el+3][k];
        acc[0][0]+=a0*b.x; acc[0][1]+=a0*b.y; acc[0][2]+=a0*b.z; acc[0][3]+=a0*b.w;
        acc[1][0]+=a1*b.x; acc[1][1]+=a1*b.y; acc[1][2]+=a1*b.z; acc[1][3]+=a1*b.w;
        acc[2][0]+=a2*b.x; acc[2][1]+=a2*b.y; acc[2][2]+=a2*b.z; acc[2][3]+=a2*b.w;
        acc[3][0]+=a3*b.x; acc[3][1]+=a3*b.y; acc[3][2]+=a3*b.z; acc[3][3]+=a3*b.w;
    }
    float mk0 = mask[n*E + e0 + el + 0];
    float mk1 = mask[n*E + e0 + el + 1];
    float mk2 = mask[n*E + e0 + el + 2];
    float mk3 = mask[n*E + e0 + el + 3];

    __syncthreads();                           // all Xs reads done; reuse as Hs
    float* HsB = &Xs[0][0];                    // Hs[e][d], row pitch 65
    #pragma unroll
    for (int dd = 0; dd < 4; dd++) {
        HsB[(el+0)*65 + d0+dd] = acc[0][dd]*mk0;
        HsB[(el+1)*65 + d0+dd] = acc[1][dd]*mk1;
        HsB[(el+2)*65 + d0+dd] = acc[2][dd]*mk2;
        HsB[(el+3)*65 + d0+dd] = acc[3][dd]*mk3;
    }
    __syncthreads();

    // coalesced 16B writes of both planes: task = (d, e-group of 8)
    #pragma unroll
    for (int u = 0; u < 2; u++) {
        int task = tid + u*256;                // 0..511
        int d = task >> 3, g = task & 7;
        uint32_t hv[4], lv[4];
        #pragma unroll
        for (int p = 0; p < 4; p++) {
            float v0 = HsB[(g*8 + 2*p + 0)*65 + d];
            float v1 = HsB[(g*8 + 2*p + 1)*65 + d];
            __nv_bfloat16 h0 = __float2bfloat16(v0);
            __nv_bfloat16 h1 = __float2bfloat16(v1);
            __nv_bfloat162 hp = __halves2bfloat162(h0, h1);
            hv[p] = *(uint32_t*)&hp;
            __nv_bfloat162 lp = __halves2bfloat162(
                __float2bfloat16(v0 - __bfloat162float(h0)),
                __float2bfloat16(v1 - __bfloat162float(h1)));
            lv[p] = *(uint32_t*)&lp;
        }
        size_t base = ((size_t)(n*OUTD + d))*E + e0 + g*8;
        *(uint4*)(g_hmT_hi + base) = make_uint4(hv[0], hv[1], hv[2], hv[3]);
        *(uint4*)(g_hmT_lo + base) = make_uint4(lv[0], lv[1], lv[2], lv[3]);
    }
}

// ---------------------------------------------------------------------------
// Kernel 3: row softmax stats (MUFU __expf), one warp per row; packs adj->u8
// ---------------------------------------------------------------------------
__global__ void rowstats_kernel(const int* __restrict__ adj) {
    int base = blockIdx.x * 16;
    int n = base / E;
    __shared__ float sds[3][E];
    int tid = threadIdx.x;
    #pragma unroll
    for (int k = tid; k < 3*E; k += 512)
        sds[k >> 9][k & 511] = g_sdst[((k >> 9)*NB + n)*E + (k & 511)];
    __syncthreads();

    int warp = tid >> 5, lane = tid & 31;
    int row = base + warp;
    int i = row & (E-1);
    float sr0 = g_ssrc[(0*NB+n)*E + i];
    float sr1 = g_ssrc[(1*NB+n)*E + i];
    float sr2 = g_ssrc[(2*NB+n)*E + i];
    const int* arow = adj + (size_t)row * E;
    unsigned char* a8 = g_adj8 + (size_t)row * E;

    float sc[16];
    #pragma unroll
    for (int k = 0; k < 16; k++) {
        int j = lane + 32*k;
        int v = arow[j];
        a8[j] = (unsigned char)v;              // pack for out_kernel
        float s = -1e30f;
        if (v > 0) {
            float srr = (v == 1) ? sr0 : ((v == 2) ? sr1 : sr2);
            float t2 = srr + sds[v-1][j];
            s = (t2 >= 0.f) ? t2 : 0.2f*t2;
        }
        sc[k] = s;
    }
    float m = sc[0];
    #pragma unroll
    for (int k = 1; k < 16; k++) m = fmaxf(m, sc[k]);
    #pragma unroll
    for (int off = 16; off > 0; off >>= 1) m = fmaxf(m, __shfl_xor_sync(~0u, m, off));
    float sum = 0.f;
    #pragma unroll
    for (int k = 0; k < 16; k++) sum += __expf(sc[k] - m);
    #pragma unroll
    for (int off = 16; off > 0; off >>= 1) sum += __shfl_xor_sync(~0u, sum, off);
    if (lane == 0) { g_rmax[row] = m; g_rinvZ[row] = 1.f / sum; }
}

// ---------------------------------------------------------------------------
// Kernel 4: output GEMM on tensor cores (mma.sync bf16, hi/lo 3-product),
// SPLIT-K by 4, packed uint8 adj, __expf coef gen, RED.ADD epilogue onto
// zeroed out. grid (NB, E/128, 4)=512 blocks, 256 thr, occ 4 -> ONE wave.
// ---------------------------------------------------------------------------
__global__ void __launch_bounds__(256, 4)
out_kernel(float* __restrict__ out) {
    extern __shared__ char sm[];
    const int CPL = 64*272;        // C plane bytes: 64 i-rows x (128+8) bf16
    const int HPL = 64*144;        // H plane bytes: 64 d-rows x (64+8) bf16
    char* Chi = sm;
    char* Hhi = sm + 2*CPL;
    char* Hlo = sm + 2*CPL + HPL;
    float* sds = (float*)(sm + 2*CPL + 2*HPL);  // [3][128]
    float* ssr = sds + 384;                      // [3][64]
    float* smx = ssr + 192;                      // [64]
    float* siz = smx + 64;                       // [64]

    const int n = blockIdx.x, j0t = blockIdx.y * 128, kz = blockIdx.z;
    const int tid = threadIdx.x;
    const int w = tid >> 5, lane = tid & 31;
    const int wm = w & 3, wn = w >> 2;           // warp tile: j=wm*32, d=wn*32

    const uint32_t sbase = smem_u32(sm);

    for (int k = tid; k < 384; k += 256)
        sds[k] = g_sdst[((k>>7)*NB + n)*E + j0t + (k & 127)];

    float acc[2][4][4] = {};                     // [m16 r][n8 ct][frag]

    const uint32_t lr = lane & 7;
    const uint32_t aA0 = sbase
        + (((lane>>4)&1)*8 + lr)*272
        + (wm*32 + ((lane>>3)&1)*8)*2;
    const uint32_t aB0 = sbase + 2*CPL
        + ((uint32_t)wn*32 + ((lane>>4)&1)*8 + lr)*144
        + ((lane>>3)&1)*16;

    for (int ch = 0; ch < 2; ch++) {
        const int ic = kz*128 + ch*64;
        __syncthreads();                         // prev chunk's mma reads done

        // stage per-chunk stats
        for (int k = tid; k < 320; k += 256) {
            if (k < 192)      ssr[k]       = g_ssrc[((k>>6)*NB + n)*E + ic + (k & 63)];
            else if (k < 256) smx[k - 192] = g_rmax[n*E + ic + (k - 192)];
            else              siz[k - 256] = g_rinvZ[n*E + ic + (k - 256)];
        }
        // stage H^T hi/lo tiles
        #pragma unroll
        for (int u = 0; u < 2; u++) {
            int k = tid + u*256;
            int d = k >> 3, i16 = k & 7;
            size_t src = ((size_t)(n*OUTD + d))*E + ic + i16*8;
            *(uint4*)(Hhi + d*144 + i16*16) = *(const uint4*)(g_hmT_hi + src);
            *(uint4*)(Hlo + d*144 + i16*16) = *(const uint4*)(g_hmT_lo + src);
        }
        __syncthreads();

        // generate coef tile: warp w handles i rows {8s + w}; adj8 is L2-hot
        const unsigned char* abase = g_adj8 + ((size_t)(n*E + ic))*E + j0t;
        #pragma unroll
        for (int s = 0; s < 8; s++) {
            int i = s*8 + w;
            uint32_t a4 = *(const uint32_t*)(abase + (size_t)i*E + lane*4);
            float m = smx[i], z = siz[i];
            float s0 = ssr[i], s1 = ssr[64 + i], s2 = ssr[128 + i];
            float cf[4];
            #pragma unroll
            for (int q = 0; q < 4; q++) {
                int v = (int)((a4 >> (8*q)) & 0xFFu);
                float score = -1e30f;
                if (v > 0) {
                    float srr = (v == 1) ? s0 : ((v == 2) ? s1 : s2);
                    float t2 = srr + sds[(v-1)*128 + lane*4 + q];
                    score = (t2 >= 0.f) ? t2 : 0.2f*t2;
                }
                cf[q] = __expf(score - m) * z;
            }
            __nv_bfloat16 h0 = __float2bfloat16(cf[0]), h1 = __float2bfloat16(cf[1]);
            __nv_bfloat16 h2 = __float2bfloat16(cf[2]), h3 = __float2bfloat16(cf[3]);
            uint2 hv;
            ((__nv_bfloat162*)&hv)[0] = __halves2bfloat162(h0, h1);
            ((__nv_bfloat162*)&hv)[1] = __halves2bfloat162(h2, h3);
            uint2 lv;
            ((__nv_bfloat162*)&lv)[0] = __halves2bfloat162(
                __float2bfloat16(cf[0] - __bfloat162float(h0)),
                __float2bfloat16(cf[1] - __bfloat162float(h1)));
            ((__nv_bfloat162*)&lv)[1] = __halves2bfloat162(
                __float2bfloat16(cf[2] - __bfloat162float(h2)),
                __float2bfloat16(cf[3] - __bfloat162float(h3)));
            *(uint2*)(Chi + i*272 + lane*8)       = hv;
            *(uint2*)(Chi + CPL + i*272 + lane*8) = lv;
        }
        __syncthreads();

        // mma phase: K-chunk = 4 k16 steps
        #pragma unroll
        for (int kk = 0; kk < 4; kk++) {
            uint32_t a_h[2][4], a_l[2][4];
            #pragma unroll
            for (int r = 0; r < 2; r++) {
                uint32_t ad = aA0 + kk*16*272 + r*32;
                LDSM4_T(a_h[r], ad);
                LDSM4_T(a_l[r], ad + CPL);
            }
            #pragma unroll
            for (int cp = 0; cp < 2; cp++) {
                uint32_t b_h[4], b_l[4];
                uint32_t bd = aB0 + cp*16*144 + kk*32;
                LDSM4(b_h, bd);
                LDSM4(b_l, bd + HPL);
                #pragma unroll
                for (int r = 0; r < 2; r++) {
                    float* d0 = acc[r][cp*2 + 0];
                    float* d1 = acc[r][cp*2 + 1];
                    MMA16816(d0, a_h[r], b_h[0], b_h[1]);
                    MMA16816(d0, a_h[r], b_l[0], b_l[1]);
                    MMA16816(d0, a_l[r], b_h[0], b_h[1]);
                    MMA16816(d1, a_h[r], b_h[2], b_h[3]);
                    MMA16816(d1, a_h[r], b_l[2], b_l[3]);
                    MMA16816(d1, a_l[r], b_h[2], b_h[3]);
                }
            }
        }
    }

    // epilogue: RED.ADD (no return) onto zeroed out — removes combine kernel
    const int g = lane >> 2, t2 = (lane & 3)*2;
    #pragma unroll
    for (int r = 0; r < 2; r++) {
        #pragma unroll
        for (int ct = 0; ct < 4; ct++) {
            int j = j0t + wm*32 + r*16 + g;
            int d = wn*32 + ct*8 + t2;
            float* p = out + ((size_t)(n*E + j))*OUTD + d;
            atomicAdd(p + 0, acc[r][ct][0]);
            atomicAdd(p + 1, acc[r][ct][1]);
            atomicAdd(p + 8*OUTD + 0, acc[r][ct][2]);
            atomicAdd(p + 8*OUTD + 1, acc[r][ct][3]);
        }
    }
}

// ---------------------------------------------------------------------------
extern "C" void kernel_launch(void* const* d_in, const int* in_sizes, int n_in,
                              void* d_out, int out_size) {
    const float* x    = (const float*)d_in[0];   // input_state (32,512,128)
    const int*   adj  = (const int*)  d_in[1];   // adj (32,512,512)
    const float* qv   = (const float*)d_in[2];   // query_vec (32,128)
    const float* mask = (const float*)d_in[3];   // node_mask (32,512,1)
    const float* Wt   = (const float*)d_in[4];   // W_type (3,128,64)
    const float* at   = (const float*)d_in[5];   // a_type (3,128,1)
    const float* W1   = (const float*)d_in[6];   // qattn_W1 (3,128,128)
    const float* W2   = (const float*)d_in[7];   // qattn_W2 (3,128,128)
    float* out = (float*)d_out;                  // (32,512,64)

    const int OUT_SMEM = 2*(64*272) + 2*(64*144) + (384 + 192 + 64 + 64)*4; // 56064
    cudaFuncSetAttribute(out_kernel, cudaFuncAttributeMaxDynamicSharedMemorySize,
                         OUT_SMEM);

    cudaMemsetAsync(d_out, 0, (size_t)out_size * sizeof(float));
    prep_kernel<<<NT*NB, 128>>>(qv, Wt, at, W1, W2);
    hm_ssd_kernel<<<dim3(NB, E/64), 256>>>(x, Wt, mask);
    rowstats_kernel<<<NB*E/16, 512>>>(adj);
    out_kernel<<<dim3(NB, E/128, 4), 256, OUT_SMEM>>>(out);
}